// round 12
// baseline (speedup 1.0000x reference)
#include <cuda_runtime.h>
#include <cuda_fp16.h>
#include <cstdint>
#include <math.h>

#define N_TOK 4096
#define DD 1024
#define EE 8
#define HH 2048
#define CAP 4096
#define HROWS (2 * N_TOK + 128)

#define TM 128           // CTA rows
#define TN 128           // CTA cols
#define NT 256           // 8 warps: 2(m) x 4(n), warp tile 64x32
#define KC 64            // fp16 k-elements per chunk = 128 bytes/row
#define SROW 144         // 128B data + 16B pad
#define AO  0            // A:   128 rows x 144 = 18432
#define BHO 18432        // Bhi: 128 rows x 144
#define BLO 36864        // Blo: 128 rows x 144
#define STAGEB 55296
#define NSTAGE 2
#define SMEM_BYTES (NSTAGE * STAGEB)   // 110592 -> 2 CTAs/SM

#define NCH1 (DD / KC)   // 16
#define NCH2 (HH / KC)   // 32

// ---------------- scratch ----------------------------------------------------
__device__ int   g_cnt[EE];
__device__ int   g_tok[EE * CAP];
__device__ float g_gate[EE * CAP];
__device__ __align__(256) __half g_x[(size_t)N_TOK * DD];               // single fp16
__device__ __align__(256) __half g_w1_hi[(size_t)EE * HH * DD];         // [e][n=H][k=D]
__device__ __align__(256) __half g_w1_lo[(size_t)EE * HH * DD];
__device__ __align__(256) __half g_w2_hi[(size_t)EE * DD * HH];         // [e][n=D][k=H]
__device__ __align__(256) __half g_w2_lo[(size_t)EE * DD * HH];
__device__ __align__(256) __half g_h[(size_t)HROWS * HH];               // single fp16

// ---------------- PTX helpers -------------------------------------------------
__device__ __forceinline__ uint32_t smem_u32(const void* p) {
    uint32_t a;
    asm("{ .reg .u64 t; cvta.to.shared.u64 t, %1; cvt.u32.u64 %0, t; }"
        : "=r"(a) : "l"(p));
    return a;
}
__device__ __forceinline__ void cp16(uint32_t dst, const void* src, int sz) {
    asm volatile("cp.async.cg.shared.global [%0], [%1], 16, %2;"
                 :: "r"(dst), "l"(src), "r"(sz));
}
#define CP_COMMIT() asm volatile("cp.async.commit_group;" ::: "memory")
#define CP_WAIT1()  asm volatile("cp.async.wait_group 1;" ::: "memory")

#define LDSM4(R, a) \
    asm volatile("ldmatrix.sync.aligned.m8n8.x4.shared.b16 {%0,%1,%2,%3}, [%4];" \
                 : "=r"((R)[0]), "=r"((R)[1]), "=r"((R)[2]), "=r"((R)[3]) : "r"(a))

#define MMA(C, A, B0, B1) \
    asm volatile("mma.sync.aligned.m16n8k16.row.col.f32.f16.f16.f32 " \
                 "{%0,%1,%2,%3}, {%4,%5,%6,%7}, {%8,%9}, {%0,%1,%2,%3};" \
                 : "+f"((C)[0]), "+f"((C)[1]), "+f"((C)[2]), "+f"((C)[3]) \
                 : "r"((A)[0]), "r"((A)[1]), "r"((A)[2]), "r"((A)[3]), \
                   "r"(B0), "r"(B1))

// ---------------- pre: zero out + counters ------------------------------------
__global__ void k_pre(float* __restrict__ out, int n4) {
    int i = blockIdx.x * blockDim.x + threadIdx.x;
    if (i < n4) ((float4*)out)[i] = make_float4(0.f, 0.f, 0.f, 0.f);
    if (blockIdx.x == 0 && threadIdx.x < EE) g_cnt[threadIdx.x] = 0;
}

// ---------------- conv_w: transpose + fp16 split both weights -----------------
// z<EE: W1 (K=DD,N=HH); z>=EE: W2 (K=HH,N=DD)
__global__ void k_conv_w(const float* __restrict__ W1f,
                         const float* __restrict__ W2f) {
    __shared__ float t[32][33];
    bool isW1 = blockIdx.z < EE;
    int e = isW1 ? blockIdx.z : blockIdx.z - EE;
    int K = isW1 ? DD : HH;
    int N = isW1 ? HH : DD;
    int n0 = blockIdx.x * 32;
    int k0 = blockIdx.y * 32;
    if (n0 >= N || k0 >= K) return;
    const float* We = (isW1 ? W1f : W2f) + (size_t)e * K * N;
    for (int r = threadIdx.y; r < 32; r += 8)
        t[r][threadIdx.x] = We[(size_t)(k0 + r) * N + n0 + threadIdx.x];
    __syncthreads();
    __half* dhi = isW1 ? g_w1_hi : g_w2_hi;
    __half* dlo = isW1 ? g_w1_lo : g_w2_lo;
    size_t base = (size_t)e * K * N;
    int tid = threadIdx.y * 32 + threadIdx.x;
    int kp  = tid & 15;
    int nr0 = tid >> 4;
#pragma unroll
    for (int it = 0; it < 2; it++) {
        int r = nr0 + it * 16;
        float v0 = t[2 * kp][r];
        float v1 = t[2 * kp + 1][r];
        __half h0 = __float2half(v0), h1 = __float2half(v1);
        __half l0 = __float2half(v0 - __half2float(h0));
        __half l1 = __float2half(v1 - __half2float(h1));
        size_t o = base + (size_t)(n0 + r) * K + k0 + 2 * kp;
        __half2 h2; h2.x = h0; h2.y = h1;
        __half2 l2; l2.x = l0; l2.y = l1;
        *(__half2*)(dhi + o) = h2;
        *(__half2*)(dlo + o) = l2;
    }
}

// ---------------- router (fused x -> fp16) ------------------------------------
__global__ void k_router(const float* __restrict__ x,
                         const float* __restrict__ Wr,
                         const float* __restrict__ br) {
    int tok  = (blockIdx.x * blockDim.x + threadIdx.x) >> 5;
    int lane = threadIdx.x & 31;
    if (tok >= N_TOK) return;
    const float* xr = x + (size_t)tok * DD;
    __half* xh = g_x + (size_t)tok * DD;
    float acc[EE];
#pragma unroll
    for (int e = 0; e < EE; e++) acc[e] = 0.f;
    for (int d = lane; d < DD; d += 32) {
        float xv = xr[d];
        xh[d] = __float2half(xv);
        const float* w = Wr + d * EE;
#pragma unroll
        for (int e = 0; e < EE; e++) acc[e] += xv * w[e];
    }
#pragma unroll
    for (int e = 0; e < EE; e++) {
#pragma unroll
        for (int o = 16; o > 0; o >>= 1)
            acc[e] += __shfl_down_sync(0xffffffffu, acc[e], o);
    }
    if (lane == 0) {
        float lg[EE];
#pragma unroll
        for (int e = 0; e < EE; e++) lg[e] = acc[e] + br[e];
        int i1 = 0;
#pragma unroll
        for (int e = 1; e < EE; e++) if (lg[e] > lg[i1]) i1 = e;
        int i2 = (i1 == 0) ? 1 : 0;
#pragma unroll
        for (int e = 0; e < EE; e++)
            if (e != i1 && lg[e] > lg[i2]) i2 = e;
        float e2 = expf(lg[i2] - lg[i1]);
        float s  = 1.0f + e2;
        int s1 = atomicAdd(&g_cnt[i1], 1);
        g_tok[i1 * CAP + s1]  = tok;
        g_gate[i1 * CAP + s1] = 1.0f / s;
        int s2 = atomicAdd(&g_cnt[i2], 1);
        g_tok[i2 * CAP + s2]  = tok;
        g_gate[i2 * CAP + s2] = e2 / s;
    }
}

// ---------------- HMMA chunk: warp tile 64(m) x 32(n), 2-product fp16 ---------
// ILP-ordered: all LDSM, then 16 independent hi MMAs, then 16 lo MMAs.
__device__ __forceinline__ void hmma_chunk(uint32_t st, int mw, int nw, int lane,
                                           float c[4][4][4]) {
    uint32_t arow = lane & 15;
    uint32_t acol = (lane >> 4) * 16;
#pragma unroll
    for (int ks = 0; ks < 4; ks++) {
        uint32_t kb = ks * 32 + acol;
        uint32_t a[4][4], bh[2][4], bl[2][4];
#pragma unroll
        for (int mf = 0; mf < 4; mf++)
            LDSM4(a[mf], st + AO + (uint32_t)(mw * 64 + mf * 16 + arow) * SROW + kb);
#pragma unroll
        for (int p = 0; p < 2; p++) {
            uint32_t ro = (uint32_t)(nw * 32 + p * 16 + arow) * SROW + kb;
            LDSM4(bh[p], st + BHO + ro);
            LDSM4(bl[p], st + BLO + ro);
        }
#pragma unroll
        for (int p = 0; p < 2; p++)
#pragma unroll
            for (int mf = 0; mf < 4; mf++) {
                MMA(c[mf][2 * p],     a[mf], bh[p][0], bh[p][2]);
                MMA(c[mf][2 * p + 1], a[mf], bh[p][1], bh[p][3]);
            }
#pragma unroll
        for (int p = 0; p < 2; p++)
#pragma unroll
            for (int mf = 0; mf < 4; mf++) {
                MMA(c[mf][2 * p],     a[mf], bl[p][0], bl[p][2]);
                MMA(c[mf][2 * p + 1], a[mf], bl[p][1], bl[p][3]);
            }
    }
}

// issue one chunk's async loads: 256 threads x 12 cp16 = 55KB
__device__ __forceinline__ void load_fp16(
    uint32_t st, const char* aP, const char* bH, const char* bL,
    int szA, int tid, int kbyte) {
    int row = tid >> 1;              // 0..127
    int j0  = (tid & 1) * 4;
#pragma unroll
    for (int j = 0; j < 4; j++) {
        uint32_t so = (uint32_t)row * SROW + (j0 + j) * 16;
        int go = kbyte + (j0 + j) * 16;
        cp16(st + AO  + so, aP + go, szA);
        cp16(st + BHO + so, bH + go, 16);
        cp16(st + BLO + so, bL + go, 16);
    }
}

// ---------------- GEMM1: h = relu(Xg @ W1^T + b1) -> fp16 ---------------------
__global__ void __launch_bounds__(NT, 2) k_mm1(const float* __restrict__ b1) {
    extern __shared__ char smem[];
    int e   = blockIdx.z;
    int cnt = g_cnt[e];
    int m0  = blockIdx.y * TM;
    if (m0 >= cnt) return;
    int n0  = blockIdx.x * TN;
    int off = 0;
    for (int i = 0; i < e; i++) off += g_cnt[i];
    int tid = threadIdx.x, wid = tid >> 5, lane = tid & 31;
    int mw = wid & 1, nw = wid >> 1;
    uint32_t sbase = smem_u32(smem);

    int drow = tid >> 1;
    bool rokA = (m0 + drow) < cnt;
    int tokA = rokA ? g_tok[e * CAP + m0 + drow] : 0;
    const char* aP = (const char*)(g_x + (size_t)tokA * DD);
    const char* bH = (const char*)(g_w1_hi + ((size_t)e * HH + n0 + drow) * DD);
    const char* bL = (const char*)(g_w1_lo + ((size_t)e * HH + n0 + drow) * DD);
    int szA = rokA ? 16 : 0;

    float c[4][4][4];
#pragma unroll
    for (int i = 0; i < 4; i++)
#pragma unroll
        for (int j = 0; j < 4; j++)
#pragma unroll
            for (int q = 0; q < 4; q++) c[i][j][q] = 0.f;

    load_fp16(sbase, aP, bH, bL, szA, tid, 0);
    CP_COMMIT();
    for (int ch = 0; ch < NCH1; ch++) {
        if (ch + 1 < NCH1)
            load_fp16(sbase + ((ch + 1) & 1) * STAGEB, aP, bH, bL,
                      szA, tid, (ch + 1) * (KC * 2));
        CP_COMMIT();
        CP_WAIT1();
        __syncthreads();
        hmma_chunk(sbase + (ch & 1) * STAGEB, mw, nw, lane, c);
        __syncthreads();
    }

    // epilogue: bias + relu, single-fp16 store
    const float* b1e = b1 + (size_t)e * HH + n0;
#pragma unroll
    for (int mf = 0; mf < 4; mf++) {
#pragma unroll
        for (int rr = 0; rr < 2; rr++) {
            int row = mw * 64 + mf * 16 + (lane >> 2) + rr * 8;
            int m = m0 + row;
            if (m >= cnt) continue;
            __half* ph = g_h + (size_t)(off + m) * HH + n0;
#pragma unroll
            for (int j = 0; j < 4; j++) {
                int col = nw * 32 + j * 8 + 2 * (lane & 3);
                float v0 = fmaxf(c[mf][j][rr * 2 + 0] + b1e[col],     0.f);
                float v1 = fmaxf(c[mf][j][rr * 2 + 1] + b1e[col + 1], 0.f);
                __half2 hv; hv.x = __float2half(v0); hv.y = __float2half(v1);
                *(__half2*)(ph + col) = hv;
            }
        }
    }
}

// ---------------- GEMM2: out[tok] += gate * (h @ W2^T + b2) -------------------
__global__ void __launch_bounds__(NT, 2) k_mm2(const float* __restrict__ b2,
                                               float* __restrict__ out) {
    extern __shared__ char smem[];
    int e   = blockIdx.z;
    int cnt = g_cnt[e];
    int m0  = blockIdx.y * TM;
    if (m0 >= cnt) return;
    int n0  = blockIdx.x * TN;
    int off = 0;
    for (int i = 0; i < e; i++) off += g_cnt[i];
    int tid = threadIdx.x, wid = tid >> 5, lane = tid & 31;
    int mw = wid & 1, nw = wid >> 1;
    uint32_t sbase = smem_u32(smem);

    int drow = tid >> 1;
    bool rokA = (m0 + drow) < cnt;
    const char* aP = (const char*)(g_h + (size_t)(off + m0 + drow) * HH);
    const char* bH = (const char*)(g_w2_hi + ((size_t)e * DD + n0 + drow) * HH);
    const char* bL = (const char*)(g_w2_lo + ((size_t)e * DD + n0 + drow) * HH);
    int szA = rokA ? 16 : 0;

    float c[4][4][4];
#pragma unroll
    for (int i = 0; i < 4; i++)
#pragma unroll
        for (int j = 0; j < 4; j++)
#pragma unroll
            for (int q = 0; q < 4; q++) c[i][j][q] = 0.f;

    load_fp16(sbase, aP, bH, bL, szA, tid, 0);
    CP_COMMIT();
    for (int ch = 0; ch < NCH2; ch++) {
        if (ch + 1 < NCH2)
            load_fp16(sbase + ((ch + 1) & 1) * STAGEB, aP, bH, bL,
                      szA, tid, (ch + 1) * (KC * 2));
        CP_COMMIT();
        CP_WAIT1();
        __syncthreads();
        hmma_chunk(sbase + (ch & 1) * STAGEB, mw, nw, lane, c);
        __syncthreads();
    }

    const float* b2e = b2 + (size_t)e * DD + n0;
#pragma unroll
    for (int mf = 0; mf < 4; mf++) {
#pragma unroll
        for (int rr = 0; rr < 2; rr++) {
            int row = mw * 64 + mf * 16 + (lane >> 2) + rr * 8;
            int m = m0 + row;
            if (m >= cnt) continue;
            int   tok  = g_tok[e * CAP + m];
            float gate = g_gate[e * CAP + m];
            float* orow = out + (size_t)tok * DD + n0;
#pragma unroll
            for (int j = 0; j < 4; j++) {
                int col = nw * 32 + j * 8 + 2 * (lane & 3);
                atomicAdd(orow + col,
                          gate * (c[mf][j][rr * 2 + 0] + b2e[col]));
                atomicAdd(orow + col + 1,
                          gate * (c[mf][j][rr * 2 + 1] + b2e[col + 1]));
            }
        }
    }
}

// ---------------- launch ------------------------------------------------------
extern "C" void kernel_launch(void* const* d_in, const int* in_sizes, int n_in,
                              void* d_out, int out_size) {
    const float* x  = (const float*)d_in[0];
    const float* Wr = (const float*)d_in[1];
    const float* br = (const float*)d_in[2];
    const float* W1 = (const float*)d_in[3];
    const float* b1 = (const float*)d_in[4];
    const float* W2 = (const float*)d_in[5];
    const float* b2 = (const float*)d_in[6];
    float* out = (float*)d_out;

    cudaFuncSetAttribute(k_mm1, cudaFuncAttributeMaxDynamicSharedMemorySize, SMEM_BYTES);
    cudaFuncSetAttribute(k_mm2, cudaFuncAttributeMaxDynamicSharedMemorySize, SMEM_BYTES);

    int n4 = out_size / 4;
    k_pre<<<(n4 + 255) / 256, 256>>>(out, n4);                            // 0
    k_conv_w<<<dim3(64, 64, 2 * EE), dim3(32, 8)>>>(W1, W2);              // 1
    k_router<<<(N_TOK * 32 + 255) / 256, 256>>>(x, Wr, br);               // 2
    k_mm1<<<dim3(HH / TN, CAP / TM, EE), NT, SMEM_BYTES>>>(b1);           // 3 (profiled)
    k_mm2<<<dim3(DD / TN, CAP / TM, EE), NT, SMEM_BYTES>>>(b2, out);      // 4
}

// round 13
// speedup vs baseline: 1.5196x; 1.5196x over previous
#include <cuda_runtime.h>
#include <cuda_fp16.h>
#include <cstdint>
#include <math.h>

#define N_TOK 4096
#define DD 1024
#define EE 8
#define HH 2048
#define CAP 4096
#define HROWS (2 * N_TOK + 256)

#define TM 256           // CTA rows
#define TN 128           // CTA cols
#define NT 512           // 16 warps: 4(m) x 4(n), warp tile 64x32
#define KC 64            // fp16 k-elements per chunk = 128 bytes/row
#define SROW 144         // 128B data + 16B pad
#define AO  0            // A: 256 rows x 144 = 36864
#define BO  36864        // B: 128 rows x 144 = 18432
#define STAGEB 55296
#define NSTAGE 3
#define SMEM_BYTES (NSTAGE * STAGEB)   // 165888

#define NCH1 (DD / KC)   // 16
#define NCH2 (HH / KC)   // 32

// ---------------- scratch ----------------------------------------------------
__device__ int   g_cnt[EE];
__device__ int   g_tok[EE * CAP];
__device__ float g_gate[EE * CAP];
__device__ __align__(256) __half g_x[(size_t)N_TOK * DD];           // fp16
__device__ __align__(256) __half g_w1[(size_t)EE * HH * DD];        // [e][n=H][k=D]
__device__ __align__(256) __half g_w2[(size_t)EE * DD * HH];        // [e][n=D][k=H]
__device__ __align__(256) __half g_h[(size_t)HROWS * HH];           // fp16

// ---------------- PTX helpers -------------------------------------------------
__device__ __forceinline__ uint32_t smem_u32(const void* p) {
    uint32_t a;
    asm("{ .reg .u64 t; cvta.to.shared.u64 t, %1; cvt.u32.u64 %0, t; }"
        : "=r"(a) : "l"(p));
    return a;
}
__device__ __forceinline__ void cp16(uint32_t dst, const void* src, int sz) {
    asm volatile("cp.async.cg.shared.global [%0], [%1], 16, %2;"
                 :: "r"(dst), "l"(src), "r"(sz));
}
#define CP_COMMIT() asm volatile("cp.async.commit_group;" ::: "memory")
#define CP_WAIT2()  asm volatile("cp.async.wait_group 2;" ::: "memory")

#define LDSM4(R, a) \
    asm volatile("ldmatrix.sync.aligned.m8n8.x4.shared.b16 {%0,%1,%2,%3}, [%4];" \
                 : "=r"((R)[0]), "=r"((R)[1]), "=r"((R)[2]), "=r"((R)[3]) : "r"(a))

#define MMA(C, A, B0, B1) \
    asm volatile("mma.sync.aligned.m16n8k16.row.col.f32.f16.f16.f32 " \
                 "{%0,%1,%2,%3}, {%4,%5,%6,%7}, {%8,%9}, {%0,%1,%2,%3};" \
                 : "+f"((C)[0]), "+f"((C)[1]), "+f"((C)[2]), "+f"((C)[3]) \
                 : "r"((A)[0]), "r"((A)[1]), "r"((A)[2]), "r"((A)[3]), \
                   "r"(B0), "r"(B1))

// ---------------- pre: zero out + counters ------------------------------------
__global__ void k_pre(float* __restrict__ out, int n4) {
    int i = blockIdx.x * blockDim.x + threadIdx.x;
    if (i < n4) ((float4*)out)[i] = make_float4(0.f, 0.f, 0.f, 0.f);
    if (blockIdx.x == 0 && threadIdx.x < EE) g_cnt[threadIdx.x] = 0;
}

// ---------------- conv_w: transpose + fp16 cast both weights ------------------
// z<EE: W1 (K=DD,N=HH); z>=EE: W2 (K=HH,N=DD)
__global__ void k_conv_w(const float* __restrict__ W1f,
                         const float* __restrict__ W2f) {
    __shared__ float t[32][33];
    bool isW1 = blockIdx.z < EE;
    int e = isW1 ? blockIdx.z : blockIdx.z - EE;
    int K = isW1 ? DD : HH;
    int N = isW1 ? HH : DD;
    int n0 = blockIdx.x * 32;
    int k0 = blockIdx.y * 32;
    if (n0 >= N || k0 >= K) return;
    const float* We = (isW1 ? W1f : W2f) + (size_t)e * K * N;
    for (int r = threadIdx.y; r < 32; r += 8)
        t[r][threadIdx.x] = We[(size_t)(k0 + r) * N + n0 + threadIdx.x];
    __syncthreads();
    __half* dw = isW1 ? g_w1 : g_w2;
    size_t base = (size_t)e * K * N;
    int tid = threadIdx.y * 32 + threadIdx.x;
    int kp  = tid & 15;
    int nr0 = tid >> 4;
#pragma unroll
    for (int it = 0; it < 2; it++) {
        int r = nr0 + it * 16;
        __half2 h2;
        h2.x = __float2half(t[2 * kp][r]);
        h2.y = __float2half(t[2 * kp + 1][r]);
        *(__half2*)(dw + base + (size_t)(n0 + r) * K + k0 + 2 * kp) = h2;
    }
}

// ---------------- router (fused x -> fp16) ------------------------------------
__global__ void k_router(const float* __restrict__ x,
                         const float* __restrict__ Wr,
                         const float* __restrict__ br) {
    int tok  = (blockIdx.x * blockDim.x + threadIdx.x) >> 5;
    int lane = threadIdx.x & 31;
    if (tok >= N_TOK) return;
    const float* xr = x + (size_t)tok * DD;
    __half* xh = g_x + (size_t)tok * DD;
    float acc[EE];
#pragma unroll
    for (int e = 0; e < EE; e++) acc[e] = 0.f;
    for (int d = lane; d < DD; d += 32) {
        float xv = xr[d];
        xh[d] = __float2half(xv);
        const float* w = Wr + d * EE;
#pragma unroll
        for (int e = 0; e < EE; e++) acc[e] += xv * w[e];
    }
#pragma unroll
    for (int e = 0; e < EE; e++) {
#pragma unroll
        for (int o = 16; o > 0; o >>= 1)
            acc[e] += __shfl_down_sync(0xffffffffu, acc[e], o);
    }
    if (lane == 0) {
        float lg[EE];
#pragma unroll
        for (int e = 0; e < EE; e++) lg[e] = acc[e] + br[e];
        int i1 = 0;
#pragma unroll
        for (int e = 1; e < EE; e++) if (lg[e] > lg[i1]) i1 = e;
        int i2 = (i1 == 0) ? 1 : 0;
#pragma unroll
        for (int e = 0; e < EE; e++)
            if (e != i1 && lg[e] > lg[i2]) i2 = e;
        float e2 = expf(lg[i2] - lg[i1]);
        float s  = 1.0f + e2;
        int s1 = atomicAdd(&g_cnt[i1], 1);
        g_tok[i1 * CAP + s1]  = tok;
        g_gate[i1 * CAP + s1] = 1.0f / s;
        int s2 = atomicAdd(&g_cnt[i2], 1);
        g_tok[i2 * CAP + s2]  = tok;
        g_gate[i2 * CAP + s2] = e2 / s;
    }
}

// ---------------- HMMA chunk: warp tile 64(m) x 32(n), plain fp16 -------------
__device__ __forceinline__ void hmma_chunk(uint32_t st, int mw, int nw, int lane,
                                           float c[4][4][4]) {
    uint32_t arow = lane & 15;
    uint32_t acol = (lane >> 4) * 16;
#pragma unroll
    for (int ks = 0; ks < 4; ks++) {
        uint32_t kb = ks * 32 + acol;
        uint32_t a[4][4], b[2][4];
#pragma unroll
        for (int mf = 0; mf < 4; mf++)
            LDSM4(a[mf], st + AO + (uint32_t)(mw * 64 + mf * 16 + arow) * SROW + kb);
#pragma unroll
        for (int p = 0; p < 2; p++)
            LDSM4(b[p], st + BO + (uint32_t)(nw * 32 + p * 16 + arow) * SROW + kb);
#pragma unroll
        for (int p = 0; p < 2; p++)
#pragma unroll
            for (int mf = 0; mf < 4; mf++) {
                MMA(c[mf][2 * p],     a[mf], b[p][0], b[p][2]);
                MMA(c[mf][2 * p + 1], a[mf], b[p][1], b[p][3]);
            }
    }
}

// issue one chunk's async loads: 512 threads, A 4 cp16 + B 2 cp16 each
__device__ __forceinline__ void load_fp16(
    uint32_t st, const char* aP, const char* bP, int szA, int tid, int kbyte) {
    int rowA = tid >> 1;             // 0..255
    int jA   = (tid & 1) * 4;
#pragma unroll
    for (int j = 0; j < 4; j++)
        cp16(st + AO + (uint32_t)rowA * SROW + (jA + j) * 16,
             aP + kbyte + (jA + j) * 16, szA);
    int rowB = tid >> 2;             // 0..127
    int jB   = (tid & 3) * 2;
#pragma unroll
    for (int j = 0; j < 2; j++)
        cp16(st + BO + (uint32_t)rowB * SROW + (jB + j) * 16,
             bP + kbyte + (jB + j) * 16, 16);
}

// ---------------- GEMM1: h = relu(Xg @ W1^T + b1) -> fp16 ---------------------
__global__ void __launch_bounds__(NT) k_mm1(const float* __restrict__ b1) {
    extern __shared__ char smem[];
    int e   = blockIdx.z;
    int cnt = g_cnt[e];
    int m0  = blockIdx.y * TM;
    if (m0 >= cnt) return;
    int n0  = blockIdx.x * TN;
    int off = 0;
    for (int i = 0; i < e; i++) off += g_cnt[i];
    int tid = threadIdx.x, wid = tid >> 5, lane = tid & 31;
    int mw = wid & 3, nw = wid >> 2;
    uint32_t sbase = smem_u32(smem);

    int drow = tid >> 1;
    bool rokA = (m0 + drow) < cnt;
    int tokA = rokA ? g_tok[e * CAP + m0 + drow] : 0;
    const char* aP = (const char*)(g_x + (size_t)tokA * DD);
    const char* bP = (const char*)(g_w1 + ((size_t)e * HH + n0 + (tid >> 2)) * DD);
    int szA = rokA ? 16 : 0;

    float c[4][4][4];
#pragma unroll
    for (int i = 0; i < 4; i++)
#pragma unroll
        for (int j = 0; j < 4; j++)
#pragma unroll
            for (int q = 0; q < 4; q++) c[i][j][q] = 0.f;

    load_fp16(sbase, aP, bP, szA, tid, 0);
    CP_COMMIT();
    load_fp16(sbase + STAGEB, aP, bP, szA, tid, KC * 2);
    CP_COMMIT();
    for (int ch = 0; ch < NCH1; ch++) {
        if (ch + 2 < NCH1)
            load_fp16(sbase + ((ch + 2) % NSTAGE) * STAGEB, aP, bP,
                      szA, tid, (ch + 2) * (KC * 2));
        CP_COMMIT();
        CP_WAIT2();
        __syncthreads();
        hmma_chunk(sbase + (ch % NSTAGE) * STAGEB, mw, nw, lane, c);
        __syncthreads();
    }

    // epilogue: bias + relu, fp16 store
    const float* b1e = b1 + (size_t)e * HH + n0;
#pragma unroll
    for (int mf = 0; mf < 4; mf++) {
#pragma unroll
        for (int rr = 0; rr < 2; rr++) {
            int row = mw * 64 + mf * 16 + (lane >> 2) + rr * 8;
            int m = m0 + row;
            if (m >= cnt) continue;
            __half* ph = g_h + (size_t)(off + m) * HH + n0;
#pragma unroll
            for (int j = 0; j < 4; j++) {
                int col = nw * 32 + j * 8 + 2 * (lane & 3);
                float v0 = fmaxf(c[mf][j][rr * 2 + 0] + b1e[col],     0.f);
                float v1 = fmaxf(c[mf][j][rr * 2 + 1] + b1e[col + 1], 0.f);
                __half2 hv; hv.x = __float2half(v0); hv.y = __float2half(v1);
                *(__half2*)(ph + col) = hv;
            }
        }
    }
}

// ---------------- GEMM2: out[tok] += gate * (h @ W2^T + b2) -------------------
__global__ void __launch_bounds__(NT) k_mm2(const float* __restrict__ b2,
                                            float* __restrict__ out) {
    extern __shared__ char smem[];
    int e   = blockIdx.z;
    int cnt = g_cnt[e];
    int m0  = blockIdx.y * TM;
    if (m0 >= cnt) return;
    int n0  = blockIdx.x * TN;
    int off = 0;
    for (int i = 0; i < e; i++) off += g_cnt[i];
    int tid = threadIdx.x, wid = tid >> 5, lane = tid & 31;
    int mw = wid & 3, nw = wid >> 2;
    uint32_t sbase = smem_u32(smem);

    int drow = tid >> 1;
    bool rokA = (m0 + drow) < cnt;
    const char* aP = (const char*)(g_h + (size_t)(off + m0 + drow) * HH);
    const char* bP = (const char*)(g_w2 + ((size_t)e * DD + n0 + (tid >> 2)) * HH);
    int szA = rokA ? 16 : 0;

    float c[4][4][4];
#pragma unroll
    for (int i = 0; i < 4; i++)
#pragma unroll
        for (int j = 0; j < 4; j++)
#pragma unroll
            for (int q = 0; q < 4; q++) c[i][j][q] = 0.f;

    load_fp16(sbase, aP, bP, szA, tid, 0);
    CP_COMMIT();
    load_fp16(sbase + STAGEB, aP, bP, szA, tid, KC * 2);
    CP_COMMIT();
    for (int ch = 0; ch < NCH2; ch++) {
        if (ch + 2 < NCH2)
            load_fp16(sbase + ((ch + 2) % NSTAGE) * STAGEB, aP, bP,
                      szA, tid, (ch + 2) * (KC * 2));
        CP_COMMIT();
        CP_WAIT2();
        __syncthreads();
        hmma_chunk(sbase + (ch % NSTAGE) * STAGEB, mw, nw, lane, c);
        __syncthreads();
    }

    const float* b2e = b2 + (size_t)e * DD + n0;
#pragma unroll
    for (int mf = 0; mf < 4; mf++) {
#pragma unroll
        for (int rr = 0; rr < 2; rr++) {
            int row = mw * 64 + mf * 16 + (lane >> 2) + rr * 8;
            int m = m0 + row;
            if (m >= cnt) continue;
            int   tok  = g_tok[e * CAP + m];
            float gate = g_gate[e * CAP + m];
            float* orow = out + (size_t)tok * DD + n0;
#pragma unroll
            for (int j = 0; j < 4; j++) {
                int col = nw * 32 + j * 8 + 2 * (lane & 3);
                atomicAdd(orow + col,
                          gate * (c[mf][j][rr * 2 + 0] + b2e[col]));
                atomicAdd(orow + col + 1,
                          gate * (c[mf][j][rr * 2 + 1] + b2e[col + 1]));
            }
        }
    }
}

// ---------------- launch ------------------------------------------------------
extern "C" void kernel_launch(void* const* d_in, const int* in_sizes, int n_in,
                              void* d_out, int out_size) {
    const float* x  = (const float*)d_in[0];
    const float* Wr = (const float*)d_in[1];
    const float* br = (const float*)d_in[2];
    const float* W1 = (const float*)d_in[3];
    const float* b1 = (const float*)d_in[4];
    const float* W2 = (const float*)d_in[5];
    const float* b2 = (const float*)d_in[6];
    float* out = (float*)d_out;

    cudaFuncSetAttribute(k_mm1, cudaFuncAttributeMaxDynamicSharedMemorySize, SMEM_BYTES);
    cudaFuncSetAttribute(k_mm2, cudaFuncAttributeMaxDynamicSharedMemorySize, SMEM_BYTES);

    int n4 = out_size / 4;
    k_pre<<<(n4 + 255) / 256, 256>>>(out, n4);                            // 0
    k_conv_w<<<dim3(64, 64, 2 * EE), dim3(32, 8)>>>(W1, W2);              // 1
    k_router<<<(N_TOK * 32 + 255) / 256, 256>>>(x, Wr, br);               // 2
    k_mm1<<<dim3(HH / TN, CAP / TM, EE), NT, SMEM_BYTES>>>(b1);           // 3 (profiled)
    k_mm2<<<dim3(DD / TN, CAP / TM, EE), NT, SMEM_BYTES>>>(b2, out);      // 4
}